// round 13
// baseline (speedup 1.0000x reference)
#include <cuda_runtime.h>
#include <cuda_fp16.h>
#include <cstdint>

#define N_NODES 100000
#define N_PAIRS 640000
#define F_TOTAL 128
#define N_HEADS 8
#define HEAD_DIM 16

// fp16 per-lane layouts: node n, lane l -> uint2 = quad (features [4l,4l+4)).
__device__ uint2 g_qh[N_NODES * 32];
__device__ uint2 g_kh[N_NODES * 32];
__device__ uint2 g_vh[N_NODES * 32];

// per-pair per-head attention coefficients, original pair order (20.5 MB)
__device__ float g_alpha[(size_t)N_PAIRS * N_HEADS];

// CSR-by-idx_i machinery
__device__ int  g_cnt[N_NODES];      // zeroed inside proj_kernel each call
__device__ int  g_cursor[N_NODES];   // scan1 writes chunk-local exclusive prefix
__device__ int4 g_meta[N_PAIRS];     // {pair_id, idx_j, 0, idx_i} grouped by idx_i
#define NB1 98                        // ceil(100000/1024)
__device__ int g_bsum[NB1];           // raw per-chunk totals (scanned locally by scatter)

#define W_STRIDE 260

__global__ void __launch_bounds__(256) proj_kernel(
    const float* __restrict__ x,
    const float* __restrict__ wq,
    const float* __restrict__ wk,
    const float* __restrict__ wv)
{
    __shared__ float sq[N_HEADS * W_STRIDE];
    __shared__ float sk[N_HEADS * W_STRIDE];
    __shared__ float sv[N_HEADS * W_STRIDE];

    int gid = blockIdx.x * 256 + threadIdx.x;   // node*8 + head
    if (gid < N_NODES) g_cnt[gid] = 0;          // fused zero_cnt

    for (int i = threadIdx.x; i < N_HEADS * HEAD_DIM * HEAD_DIM; i += 256) {
        int h = i >> 8;
        int r = i & 255;
        sq[h * W_STRIDE + r] = wq[i];
        sk[h * W_STRIDE + r] = wk[i];
        sv[h * W_STRIDE + r] = wv[i];
    }
    __syncthreads();

    if (gid >= N_NODES * N_HEADS) return;
    int n = gid >> 3;
    int h = gid & 7;

    const float4* xp = reinterpret_cast<const float4*>(x + (size_t)n * F_TOTAL + h * HEAD_DIM);
    float4 xv0 = xp[0], xv1 = xp[1], xv2 = xp[2], xv3 = xp[3];
    float xr[16] = {xv0.x, xv0.y, xv0.z, xv0.w,
                    xv1.x, xv1.y, xv1.z, xv1.w,
                    xv2.x, xv2.y, xv2.z, xv2.w,
                    xv3.x, xv3.y, xv3.z, xv3.w};

    const float4* wq4 = reinterpret_cast<const float4*>(sq + h * W_STRIDE);
    const float4* wk4 = reinterpret_cast<const float4*>(sk + h * W_STRIDE);
    const float4* wv4 = reinterpret_cast<const float4*>(sv + h * W_STRIDE);

    float qo[16], ko[16], vo[16];
#pragma unroll
    for (int e = 0; e < 16; e++) {
        float aq = 0.f, ak = 0.f, av = 0.f;
#pragma unroll
        for (int d4 = 0; d4 < 4; d4++) {
            float4 a = wq4[e * 4 + d4];
            float4 b = wk4[e * 4 + d4];
            float4 c = wv4[e * 4 + d4];
            float x0 = xr[4 * d4 + 0], x1 = xr[4 * d4 + 1];
            float x2 = xr[4 * d4 + 2], x3 = xr[4 * d4 + 3];
            aq += x0 * a.x + x1 * a.y + x2 * a.z + x3 * a.w;
            ak += x0 * b.x + x1 * b.y + x2 * b.z + x3 * b.w;
            av += x0 * c.x + x1 * c.y + x2 * c.z + x3 * c.w;
        }
        qo[e] = aq; ko[e] = ak; vo[e] = av;
    }

#pragma unroll
    for (int t = 0; t < 4; t++) {
        int lane = h * 4 + t;
        half2 q01 = __floats2half2_rn(qo[4*t + 0], qo[4*t + 1]);
        half2 q23 = __floats2half2_rn(qo[4*t + 2], qo[4*t + 3]);
        half2 k01 = __floats2half2_rn(ko[4*t + 0], ko[4*t + 1]);
        half2 k23 = __floats2half2_rn(ko[4*t + 2], ko[4*t + 3]);
        half2 v01 = __floats2half2_rn(vo[4*t + 0], vo[4*t + 1]);
        half2 v23 = __floats2half2_rn(vo[4*t + 2], vo[4*t + 3]);
        uint2 qp, kp, vp;
        qp.x = *reinterpret_cast<uint32_t*>(&q01);
        qp.y = *reinterpret_cast<uint32_t*>(&q23);
        kp.x = *reinterpret_cast<uint32_t*>(&k01);
        kp.y = *reinterpret_cast<uint32_t*>(&k23);
        vp.x = *reinterpret_cast<uint32_t*>(&v01);
        vp.y = *reinterpret_cast<uint32_t*>(&v23);
        g_qh[(size_t)n * 32 + lane] = qp;
        g_kh[(size_t)n * 32 + lane] = kp;
        g_vh[(size_t)n * 32 + lane] = vp;
    }
}

// alpha pass: warp per pair, ORIGINAL pair order -> w_ij is a perfect
// sequential stream. q/k gathers hit L2-resident 25MB fp16 arrays.
__global__ void __launch_bounds__(256) alpha_kernel(
    const float* __restrict__ w_ij,
    const int*   __restrict__ idx_i,
    const int*   __restrict__ idx_j,
    const float* __restrict__ phi)
{
    int p = blockIdx.x * 8 + (threadIdx.x >> 5);
    int lane = threadIdx.x & 31;

    int i = __ldg(&idx_i[p]);
    int j = __ldg(&idx_j[p]);
    float ph = __ldg(&phi[p]);

    float4 w = __ldcs(reinterpret_cast<const float4*>(w_ij) + (size_t)p * 32 + lane);
    uint2 qp = __ldg(&g_qh[(size_t)i * 32 + lane]);
    uint2 kp = __ldg(&g_kh[(size_t)j * 32 + lane]);

    float2 q01 = __half22float2(*reinterpret_cast<half2*>(&qp.x));
    float2 q23 = __half22float2(*reinterpret_cast<half2*>(&qp.y));
    float2 k01 = __half22float2(*reinterpret_cast<half2*>(&kp.x));
    float2 k23 = __half22float2(*reinterpret_cast<half2*>(&kp.y));

    float part = q01.x * w.x * k01.x + q01.y * w.y * k01.y
               + q23.x * w.z * k23.x + q23.y * w.w * k23.y;
    part += __shfl_xor_sync(0xFFFFFFFFu, part, 1);
    part += __shfl_xor_sync(0xFFFFFFFFu, part, 2);

    if ((lane & 3) == 0)
        g_alpha[(size_t)p * 8 + (lane >> 2)] = part * 0.25f * ph;  // 1/sqrt(16)*phi
}

// histogram over idx_i + fused zeroing of the output buffer
__global__ void __launch_bounds__(256) hist_kernel(
    const int* __restrict__ idx_i,
    float4*    __restrict__ out4,
    int n4)
{
    int p = blockIdx.x * 256 + threadIdx.x;
    float4 z = make_float4(0.f, 0.f, 0.f, 0.f);
#pragma unroll
    for (int r = 0; r < 5; r++) {
        int o = p + r * N_PAIRS;
        if (o < n4) out4[o] = z;
    }
    if (p < N_PAIRS) atomicAdd(&g_cnt[idx_i[p]], 1);
}

// per-block (1024-element) exclusive scan of g_cnt into g_cursor; raw totals to g_bsum
__global__ void __launch_bounds__(256) scan1_kernel()
{
    __shared__ int sh[256];
    int t = threadIdx.x;
    int base = blockIdx.x * 1024 + t * 4;
    int v0 = (base + 0 < N_NODES) ? g_cnt[base + 0] : 0;
    int v1 = (base + 1 < N_NODES) ? g_cnt[base + 1] : 0;
    int v2 = (base + 2 < N_NODES) ? g_cnt[base + 2] : 0;
    int v3 = (base + 3 < N_NODES) ? g_cnt[base + 3] : 0;
    int s = v0 + v1 + v2 + v3;
    sh[t] = s;
    __syncthreads();
    for (int off = 1; off < 256; off <<= 1) {
        int add = (t >= off) ? sh[t - off] : 0;
        __syncthreads();
        sh[t] += add;
        __syncthreads();
    }
    int excl = sh[t] - s;
    if (base + 0 < N_NODES) g_cursor[base + 0] = excl;
    if (base + 1 < N_NODES) g_cursor[base + 1] = excl + v0;
    if (base + 2 < N_NODES) g_cursor[base + 2] = excl + v0 + v1;
    if (base + 3 < N_NODES) g_cursor[base + 3] = excl + v0 + v1 + v2;
    if (t == 255) g_bsum[blockIdx.x] = sh[255];
}

// scatter with the 98-entry chunk-offset scan done redundantly per block.
__global__ void __launch_bounds__(256) scatter_kernel(
    const int* __restrict__ idx_i,
    const int* __restrict__ idx_j)
{
    __shared__ int sh[128];
    __shared__ int sexcl[128];
    int t = threadIdx.x;

    int v = 0;
    if (t < 128) {
        v = (t < NB1) ? g_bsum[t] : 0;
        sh[t] = v;
    }
    __syncthreads();
    for (int off = 1; off < 128; off <<= 1) {
        int add = 0;
        if (t < 128 && t >= off) add = sh[t - off];
        __syncthreads();
        if (t < 128) sh[t] += add;
        __syncthreads();
    }
    if (t < 128) sexcl[t] = sh[t] - v;
    __syncthreads();

    int p = blockIdx.x * 256 + t;
    if (p < N_PAIRS) {
        int i = idx_i[p];
        int pos = atomicAdd(&g_cursor[i], 1) + sexcl[i >> 10];
        g_meta[pos] = make_int4(p, idx_j[p], 0, i);
    }
}

// Edge-parallel segmented reduction. Hot loop touches only alpha (32B/warp,
// L2-resident) and v (256B/warp, L2-resident) — w/q/k never appear here.
#define EDGES_PER_WARP 16
#define WARPS_PER_BLOCK 8
#define EDGES_PER_BLOCK (EDGES_PER_WARP * WARPS_PER_BLOCK)
__global__ void __launch_bounds__(256) aggregate_kernel(float* __restrict__ out)
{
    __shared__ int4 smeta[EDGES_PER_BLOCK];
    int t = threadIdx.x;
    int wid  = t >> 5;
    int lane = t & 31;
    int mbase = wid * EDGES_PER_WARP;
    int warpBase = blockIdx.x * EDGES_PER_BLOCK + mbase;

    if (lane < EDGES_PER_WARP) smeta[mbase + lane] = g_meta[warpBase + lane];
    __syncwarp();

    int hsel = lane >> 2;   // head owned by this lane's quad

    int cur = smeta[mbase].w;
    float4 acc = make_float4(0.f, 0.f, 0.f, 0.f);

#pragma unroll
    for (int e = 0; e < EDGES_PER_WARP; e++) {
        int4 mm = smeta[mbase + e];                                     // LDS broadcast
        float alpha = __ldg(&g_alpha[(size_t)mm.x * 8 + hsel]);         // 32B/warp
        uint2 vp = __ldg(&g_vh[(size_t)mm.y * 32 + lane]);              // 256B/warp

        if (mm.w != cur) {                                              // boundary
            float* dst = out + (size_t)cur * F_TOTAL + lane * 4;
            asm volatile("red.global.add.v4.f32 [%0], {%1,%2,%3,%4};"
                         :: "l"(dst), "f"(acc.x), "f"(acc.y), "f"(acc.z), "f"(acc.w));
            cur = mm.w;
            acc = make_float4(0.f, 0.f, 0.f, 0.f);
        }

        float2 v01 = __half22float2(*reinterpret_cast<half2*>(&vp.x));
        float2 v23 = __half22float2(*reinterpret_cast<half2*>(&vp.y));
        acc.x += alpha * v01.x;
        acc.y += alpha * v01.y;
        acc.z += alpha * v23.x;
        acc.w += alpha * v23.y;
    }
    float* dst = out + (size_t)cur * F_TOTAL + lane * 4;
    asm volatile("red.global.add.v4.f32 [%0], {%1,%2,%3,%4};"
                 :: "l"(dst), "f"(acc.x), "f"(acc.y), "f"(acc.z), "f"(acc.w));
}

extern "C" void kernel_launch(void* const* d_in, const int* in_sizes, int n_in,
                              void* d_out, int out_size)
{
    const float* x      = (const float*)d_in[0];
    const float* w_ij   = (const float*)d_in[1];
    const int*   idx_i  = (const int*)  d_in[2];
    const int*   idx_j  = (const int*)  d_in[3];
    const float* phi    = (const float*)d_in[4];
    const float* wq     = (const float*)d_in[5];
    const float* wk     = (const float*)d_in[6];
    const float* wv     = (const float*)d_in[7];
    float* out = (float*)d_out;

    proj_kernel<<<(N_NODES * N_HEADS + 255) / 256, 256>>>(x, wq, wk, wv);
    alpha_kernel<<<N_PAIRS / 8, 256>>>(w_ij, idx_i, idx_j, phi);
    hist_kernel<<<(N_PAIRS + 255) / 256, 256>>>(idx_i, reinterpret_cast<float4*>(out), out_size / 4);
    scan1_kernel<<<NB1, 256>>>();
    scatter_kernel<<<(N_PAIRS + 255) / 256, 256>>>(idx_i, idx_j);
    aggregate_kernel<<<N_PAIRS / EDGES_PER_BLOCK, 256>>>(out);
}

// round 14
// speedup vs baseline: 1.2685x; 1.2685x over previous
#include <cuda_runtime.h>
#include <cuda_fp16.h>
#include <cstdint>

#define N_NODES 100000
#define N_PAIRS 640000
#define F_TOTAL 128
#define N_HEADS 8
#define HEAD_DIM 16

// q fp16: node n, lane l -> uint2 = q quad (features [4l,4l+4)) as 2x half2.
// kv fp16: node n, lane l -> uint4 = {k quad, v quad}.
__device__ uint2 g_qh[N_NODES * 32];
__device__ uint4 g_kv[N_NODES * 32];

// CSR-by-idx_i machinery
__device__ int  g_cnt[N_NODES];      // zeroed inside proj_kernel each call
__device__ int  g_cursor[N_NODES];   // scan1 writes chunk-local exclusive prefix
__device__ int4 g_meta[N_PAIRS];     // {pair_id, idx_j, phi_bits, idx_i} grouped by idx_i
#define NB1 98                        // ceil(100000/1024)
__device__ int g_bsum[NB1];           // raw per-chunk totals (scanned locally by scatter)

#define W_STRIDE 260

__global__ void __launch_bounds__(256) proj_kernel(
    const float* __restrict__ x,
    const float* __restrict__ wq,
    const float* __restrict__ wk,
    const float* __restrict__ wv)
{
    __shared__ float sq[N_HEADS * W_STRIDE];
    __shared__ float sk[N_HEADS * W_STRIDE];
    __shared__ float sv[N_HEADS * W_STRIDE];

    int gid = blockIdx.x * 256 + threadIdx.x;   // node*8 + head
    if (gid < N_NODES) g_cnt[gid] = 0;          // fused zero_cnt

    for (int i = threadIdx.x; i < N_HEADS * HEAD_DIM * HEAD_DIM; i += 256) {
        int h = i >> 8;
        int r = i & 255;
        sq[h * W_STRIDE + r] = wq[i];
        sk[h * W_STRIDE + r] = wk[i];
        sv[h * W_STRIDE + r] = wv[i];
    }
    __syncthreads();

    if (gid >= N_NODES * N_HEADS) return;
    int n = gid >> 3;
    int h = gid & 7;

    const float4* xp = reinterpret_cast<const float4*>(x + (size_t)n * F_TOTAL + h * HEAD_DIM);
    float4 xv0 = xp[0], xv1 = xp[1], xv2 = xp[2], xv3 = xp[3];
    float xr[16] = {xv0.x, xv0.y, xv0.z, xv0.w,
                    xv1.x, xv1.y, xv1.z, xv1.w,
                    xv2.x, xv2.y, xv2.z, xv2.w,
                    xv3.x, xv3.y, xv3.z, xv3.w};

    const float4* wq4 = reinterpret_cast<const float4*>(sq + h * W_STRIDE);
    const float4* wk4 = reinterpret_cast<const float4*>(sk + h * W_STRIDE);
    const float4* wv4 = reinterpret_cast<const float4*>(sv + h * W_STRIDE);

    float qo[16], ko[16], vo[16];
#pragma unroll
    for (int e = 0; e < 16; e++) {
        float aq = 0.f, ak = 0.f, av = 0.f;
#pragma unroll
        for (int d4 = 0; d4 < 4; d4++) {
            float4 a = wq4[e * 4 + d4];
            float4 b = wk4[e * 4 + d4];
            float4 c = wv4[e * 4 + d4];
            float x0 = xr[4 * d4 + 0], x1 = xr[4 * d4 + 1];
            float x2 = xr[4 * d4 + 2], x3 = xr[4 * d4 + 3];
            aq += x0 * a.x + x1 * a.y + x2 * a.z + x3 * a.w;
            ak += x0 * b.x + x1 * b.y + x2 * b.z + x3 * b.w;
            av += x0 * c.x + x1 * c.y + x2 * c.z + x3 * c.w;
        }
        qo[e] = aq; ko[e] = ak; vo[e] = av;
    }

#pragma unroll
    for (int t = 0; t < 4; t++) {
        int lane = h * 4 + t;
        half2 q01 = __floats2half2_rn(qo[4*t + 0], qo[4*t + 1]);
        half2 q23 = __floats2half2_rn(qo[4*t + 2], qo[4*t + 3]);
        uint2 qp;
        qp.x = *reinterpret_cast<uint32_t*>(&q01);
        qp.y = *reinterpret_cast<uint32_t*>(&q23);
        g_qh[(size_t)n * 32 + lane] = qp;

        half2 k01 = __floats2half2_rn(ko[4*t + 0], ko[4*t + 1]);
        half2 k23 = __floats2half2_rn(ko[4*t + 2], ko[4*t + 3]);
        half2 v01 = __floats2half2_rn(vo[4*t + 0], vo[4*t + 1]);
        half2 v23 = __floats2half2_rn(vo[4*t + 2], vo[4*t + 3]);
        uint4 kvp;
        kvp.x = *reinterpret_cast<uint32_t*>(&k01);
        kvp.y = *reinterpret_cast<uint32_t*>(&k23);
        kvp.z = *reinterpret_cast<uint32_t*>(&v01);
        kvp.w = *reinterpret_cast<uint32_t*>(&v23);
        g_kv[(size_t)n * 32 + lane] = kvp;
    }
}

// histogram over idx_i + fused zeroing of the output buffer
__global__ void __launch_bounds__(256) hist_kernel(
    const int* __restrict__ idx_i,
    float4*    __restrict__ out4,
    int n4)
{
    int p = blockIdx.x * 256 + threadIdx.x;
    float4 z = make_float4(0.f, 0.f, 0.f, 0.f);
#pragma unroll
    for (int r = 0; r < 5; r++) {
        int o = p + r * N_PAIRS;
        if (o < n4) out4[o] = z;
    }
    if (p < N_PAIRS) atomicAdd(&g_cnt[idx_i[p]], 1);
}

// per-block (1024-element) exclusive scan of g_cnt into g_cursor; raw totals to g_bsum
__global__ void __launch_bounds__(256) scan1_kernel()
{
    __shared__ int sh[256];
    int t = threadIdx.x;
    int base = blockIdx.x * 1024 + t * 4;
    int v0 = (base + 0 < N_NODES) ? g_cnt[base + 0] : 0;
    int v1 = (base + 1 < N_NODES) ? g_cnt[base + 1] : 0;
    int v2 = (base + 2 < N_NODES) ? g_cnt[base + 2] : 0;
    int v3 = (base + 3 < N_NODES) ? g_cnt[base + 3] : 0;
    int s = v0 + v1 + v2 + v3;
    sh[t] = s;
    __syncthreads();
    for (int off = 1; off < 256; off <<= 1) {
        int add = (t >= off) ? sh[t - off] : 0;
        __syncthreads();
        sh[t] += add;
        __syncthreads();
    }
    int excl = sh[t] - s;
    if (base + 0 < N_NODES) g_cursor[base + 0] = excl;
    if (base + 1 < N_NODES) g_cursor[base + 1] = excl + v0;
    if (base + 2 < N_NODES) g_cursor[base + 2] = excl + v0 + v1;
    if (base + 3 < N_NODES) g_cursor[base + 3] = excl + v0 + v1 + v2;
    if (t == 255) g_bsum[blockIdx.x] = sh[255];
}

// scatter with the 98-entry chunk-offset scan done redundantly per block
// (no scan2 launch). slot = local cursor bump + scanned chunk offset.
__global__ void __launch_bounds__(256) scatter_kernel(
    const int* __restrict__ idx_i,
    const int* __restrict__ idx_j,
    const float* __restrict__ phi)
{
    __shared__ int sh[128];
    __shared__ int sexcl[128];
    int t = threadIdx.x;

    int v = 0;
    if (t < 128) {
        v = (t < NB1) ? g_bsum[t] : 0;
        sh[t] = v;
    }
    __syncthreads();
    for (int off = 1; off < 128; off <<= 1) {
        int add = 0;
        if (t < 128 && t >= off) add = sh[t - off];
        __syncthreads();
        if (t < 128) sh[t] += add;
        __syncthreads();
    }
    if (t < 128) sexcl[t] = sh[t] - v;
    __syncthreads();

    int p = blockIdx.x * 256 + t;
    if (p < N_PAIRS) {
        int i = idx_i[p];
        int pos = atomicAdd(&g_cursor[i], 1) + sexcl[i >> 10];
        g_meta[pos] = make_int4(p, idx_j[p], __float_as_int(phi[p]), i);
    }
}

// Edge-parallel segmented reduction. Each warp owns 32 edges, stages its own
// metas with ONE full-warp coalesced load, syncs with __syncwarp only, then
// runs the interleaved single-pass body. red.global flushes carry no memory
// clobber so later edges' loads can hoist above them.
#define EDGES_PER_WARP 32
#define WARPS_PER_BLOCK 8
#define EDGES_PER_BLOCK (EDGES_PER_WARP * WARPS_PER_BLOCK)
__global__ void __launch_bounds__(256) aggregate_kernel(
    const float* __restrict__ w_ij,
    float*       __restrict__ out)
{
    __shared__ int4 smeta[EDGES_PER_BLOCK];
    int t = threadIdx.x;
    int wid  = t >> 5;
    int lane = t & 31;
    int mbase = wid * EDGES_PER_WARP;
    int warpBase = blockIdx.x * EDGES_PER_BLOCK + mbase;

    smeta[mbase + lane] = g_meta[warpBase + lane];   // full-warp coalesced stage
    __syncwarp();

    const float4* w4 = reinterpret_cast<const float4*>(w_ij);

    int cur = smeta[mbase].w;
    uint2 qp = __ldg(&g_qh[(size_t)cur * 32 + lane]);
    float2 q01 = __half22float2(*reinterpret_cast<half2*>(&qp.x));
    float2 q23 = __half22float2(*reinterpret_cast<half2*>(&qp.y));
    float4 acc = make_float4(0.f, 0.f, 0.f, 0.f);

#pragma unroll
    for (int e = 0; e < EDGES_PER_WARP; e++) {
        int4 mm = smeta[mbase + e];                                  // LDS broadcast
        float4 we = __ldcs(w4 + (size_t)mm.x * 32 + lane);           // stream
        uint4 kve = __ldg(&g_kv[(size_t)mm.y * 32 + lane]);          // gather
        float phe = __int_as_float(mm.z);

        if (mm.w != cur) {                                           // segment boundary
            float* dst = out + (size_t)cur * F_TOTAL + lane * 4;
            asm volatile("red.global.add.v4.f32 [%0], {%1,%2,%3,%4};"
                         :: "l"(dst), "f"(acc.x), "f"(acc.y), "f"(acc.z), "f"(acc.w));
            cur = mm.w;
            qp = __ldg(&g_qh[(size_t)cur * 32 + lane]);
            q01 = __half22float2(*reinterpret_cast<half2*>(&qp.x));
            q23 = __half22float2(*reinterpret_cast<half2*>(&qp.y));
            acc = make_float4(0.f, 0.f, 0.f, 0.f);
        }

        float2 k01 = __half22float2(*reinterpret_cast<half2*>(&kve.x));
        float2 k23 = __half22float2(*reinterpret_cast<half2*>(&kve.y));
        float2 v01 = __half22float2(*reinterpret_cast<half2*>(&kve.z));
        float2 v23 = __half22float2(*reinterpret_cast<half2*>(&kve.w));

        float part = q01.x * we.x * k01.x + q01.y * we.y * k01.y
                   + q23.x * we.z * k23.x + q23.y * we.w * k23.y;
        part += __shfl_xor_sync(0xFFFFFFFFu, part, 1);
        part += __shfl_xor_sync(0xFFFFFFFFu, part, 2);

        float alpha = part * 0.25f * phe;   // 1/sqrt(16)
        acc.x += alpha * v01.x;
        acc.y += alpha * v01.y;
        acc.z += alpha * v23.x;
        acc.w += alpha * v23.y;
    }
    float* dst = out + (size_t)cur * F_TOTAL + lane * 4;
    asm volatile("red.global.add.v4.f32 [%0], {%1,%2,%3,%4};"
                 :: "l"(dst), "f"(acc.x), "f"(acc.y), "f"(acc.z), "f"(acc.w));
}

extern "C" void kernel_launch(void* const* d_in, const int* in_sizes, int n_in,
                              void* d_out, int out_size)
{
    const float* x      = (const float*)d_in[0];
    const float* w_ij   = (const float*)d_in[1];
    const int*   idx_i  = (const int*)  d_in[2];
    const int*   idx_j  = (const int*)  d_in[3];
    const float* phi    = (const float*)d_in[4];
    const float* wq     = (const float*)d_in[5];
    const float* wk     = (const float*)d_in[6];
    const float* wv     = (const float*)d_in[7];
    float* out = (float*)d_out;

    proj_kernel<<<(N_NODES * N_HEADS + 255) / 256, 256>>>(x, wq, wk, wv);
    hist_kernel<<<(N_PAIRS + 255) / 256, 256>>>(idx_i, reinterpret_cast<float4*>(out), out_size / 4);
    scan1_kernel<<<NB1, 256>>>();
    scatter_kernel<<<(N_PAIRS + 255) / 256, 256>>>(idx_i, idx_j, phi);
    aggregate_kernel<<<N_PAIRS / EDGES_PER_BLOCK, 256>>>(w_ij, out);
}

// round 15
// speedup vs baseline: 1.2963x; 1.0219x over previous
#include <cuda_runtime.h>
#include <cuda_fp16.h>
#include <cstdint>

#define N_NODES 100000
#define N_PAIRS 640000
#define F_TOTAL 128
#define N_HEADS 8
#define HEAD_DIM 16

// q fp16: node n, lane l -> uint2 = q quad (features [4l,4l+4)) as 2x half2.
// kv fp16: node n, lane l -> uint4 = {k quad, v quad}.
__device__ uint2 g_qh[N_NODES * 32];
__device__ uint4 g_kv[N_NODES * 32];

// CSR-by-idx_i machinery.
// g_cnt is zeroed by the TAIL of aggregate_kernel each call (device globals
// start zeroed, so call 1 sees zeros too -> every call does identical work).
__device__ int  g_cnt[N_NODES];
__device__ int  g_cursor[N_NODES];   // scan1 writes chunk-local exclusive prefix
__device__ int4 g_meta[N_PAIRS];     // {pair_id, idx_j, phi_bits, idx_i} grouped by idx_i
#define NB1 98                        // ceil(100000/1024)
__device__ int g_bsum[NB1];           // raw per-chunk totals (scanned locally by scatter)

#define W_STRIDE 260

// proj + histogram fused: thread gid handles (node, head) projection AND,
// for gid < N_PAIRS, the idx_i histogram atomic.
__global__ void __launch_bounds__(256) projhist_kernel(
    const float* __restrict__ x,
    const float* __restrict__ wq,
    const float* __restrict__ wk,
    const float* __restrict__ wv,
    const int*   __restrict__ idx_i)
{
    __shared__ float sq[N_HEADS * W_STRIDE];
    __shared__ float sk[N_HEADS * W_STRIDE];
    __shared__ float sv[N_HEADS * W_STRIDE];

    int gid = blockIdx.x * 256 + threadIdx.x;   // node*8 + head
    if (gid < N_PAIRS) atomicAdd(&g_cnt[idx_i[gid]], 1);   // fused histogram

    for (int i = threadIdx.x; i < N_HEADS * HEAD_DIM * HEAD_DIM; i += 256) {
        int h = i >> 8;
        int r = i & 255;
        sq[h * W_STRIDE + r] = wq[i];
        sk[h * W_STRIDE + r] = wk[i];
        sv[h * W_STRIDE + r] = wv[i];
    }
    __syncthreads();

    if (gid >= N_NODES * N_HEADS) return;
    int n = gid >> 3;
    int h = gid & 7;

    const float4* xp = reinterpret_cast<const float4*>(x + (size_t)n * F_TOTAL + h * HEAD_DIM);
    float4 xv0 = xp[0], xv1 = xp[1], xv2 = xp[2], xv3 = xp[3];
    float xr[16] = {xv0.x, xv0.y, xv0.z, xv0.w,
                    xv1.x, xv1.y, xv1.z, xv1.w,
                    xv2.x, xv2.y, xv2.z, xv2.w,
                    xv3.x, xv3.y, xv3.z, xv3.w};

    const float4* wq4 = reinterpret_cast<const float4*>(sq + h * W_STRIDE);
    const float4* wk4 = reinterpret_cast<const float4*>(sk + h * W_STRIDE);
    const float4* wv4 = reinterpret_cast<const float4*>(sv + h * W_STRIDE);

    float qo[16], ko[16], vo[16];
#pragma unroll
    for (int e = 0; e < 16; e++) {
        float aq = 0.f, ak = 0.f, av = 0.f;
#pragma unroll
        for (int d4 = 0; d4 < 4; d4++) {
            float4 a = wq4[e * 4 + d4];
            float4 b = wk4[e * 4 + d4];
            float4 c = wv4[e * 4 + d4];
            float x0 = xr[4 * d4 + 0], x1 = xr[4 * d4 + 1];
            float x2 = xr[4 * d4 + 2], x3 = xr[4 * d4 + 3];
            aq += x0 * a.x + x1 * a.y + x2 * a.z + x3 * a.w;
            ak += x0 * b.x + x1 * b.y + x2 * b.z + x3 * b.w;
            av += x0 * c.x + x1 * c.y + x2 * c.z + x3 * c.w;
        }
        qo[e] = aq; ko[e] = ak; vo[e] = av;
    }

#pragma unroll
    for (int t = 0; t < 4; t++) {
        int lane = h * 4 + t;
        half2 q01 = __floats2half2_rn(qo[4*t + 0], qo[4*t + 1]);
        half2 q23 = __floats2half2_rn(qo[4*t + 2], qo[4*t + 3]);
        uint2 qp;
        qp.x = *reinterpret_cast<uint32_t*>(&q01);
        qp.y = *reinterpret_cast<uint32_t*>(&q23);
        g_qh[(size_t)n * 32 + lane] = qp;

        half2 k01 = __floats2half2_rn(ko[4*t + 0], ko[4*t + 1]);
        half2 k23 = __floats2half2_rn(ko[4*t + 2], ko[4*t + 3]);
        half2 v01 = __floats2half2_rn(vo[4*t + 0], vo[4*t + 1]);
        half2 v23 = __floats2half2_rn(vo[4*t + 2], vo[4*t + 3]);
        uint4 kvp;
        kvp.x = *reinterpret_cast<uint32_t*>(&k01);
        kvp.y = *reinterpret_cast<uint32_t*>(&k23);
        kvp.z = *reinterpret_cast<uint32_t*>(&v01);
        kvp.w = *reinterpret_cast<uint32_t*>(&v23);
        g_kv[(size_t)n * 32 + lane] = kvp;
    }
}

// per-block (1024-element) exclusive scan of g_cnt into g_cursor; raw totals to g_bsum
__global__ void __launch_bounds__(256) scan1_kernel()
{
    __shared__ int sh[256];
    int t = threadIdx.x;
    int base = blockIdx.x * 1024 + t * 4;
    int v0 = (base + 0 < N_NODES) ? g_cnt[base + 0] : 0;
    int v1 = (base + 1 < N_NODES) ? g_cnt[base + 1] : 0;
    int v2 = (base + 2 < N_NODES) ? g_cnt[base + 2] : 0;
    int v3 = (base + 3 < N_NODES) ? g_cnt[base + 3] : 0;
    int s = v0 + v1 + v2 + v3;
    sh[t] = s;
    __syncthreads();
    for (int off = 1; off < 256; off <<= 1) {
        int add = (t >= off) ? sh[t - off] : 0;
        __syncthreads();
        sh[t] += add;
        __syncthreads();
    }
    int excl = sh[t] - s;
    if (base + 0 < N_NODES) g_cursor[base + 0] = excl;
    if (base + 1 < N_NODES) g_cursor[base + 1] = excl + v0;
    if (base + 2 < N_NODES) g_cursor[base + 2] = excl + v0 + v1;
    if (base + 3 < N_NODES) g_cursor[base + 3] = excl + v0 + v1 + v2;
    if (t == 255) g_bsum[blockIdx.x] = sh[255];
}

// scatter (with redundant 98-entry chunk-offset scan) + fused zeroing of out.
__global__ void __launch_bounds__(256) scatter_kernel(
    const int* __restrict__ idx_i,
    const int* __restrict__ idx_j,
    const float* __restrict__ phi,
    float4*    __restrict__ out4,
    int n4)
{
    __shared__ int sh[128];
    __shared__ int sexcl[128];
    int t = threadIdx.x;
    int p = blockIdx.x * 256 + t;

    float4 z = make_float4(0.f, 0.f, 0.f, 0.f);
#pragma unroll
    for (int r = 0; r < 5; r++) {
        int o = p + r * N_PAIRS;
        if (o < n4) out4[o] = z;
    }

    int v = 0;
    if (t < 128) {
        v = (t < NB1) ? g_bsum[t] : 0;
        sh[t] = v;
    }
    __syncthreads();
    for (int off = 1; off < 128; off <<= 1) {
        int add = 0;
        if (t < 128 && t >= off) add = sh[t - off];
        __syncthreads();
        if (t < 128) sh[t] += add;
        __syncthreads();
    }
    if (t < 128) sexcl[t] = sh[t] - v;
    __syncthreads();

    if (p < N_PAIRS) {
        int i = idx_i[p];
        int pos = atomicAdd(&g_cursor[i], 1) + sexcl[i >> 10];
        g_meta[pos] = make_int4(p, idx_j[p], __float_as_int(phi[p]), i);
    }
}

// Edge-parallel segmented reduction (round-14 body, unchanged) + g_cnt reset
// for the next invocation.
#define EDGES_PER_WARP 32
#define WARPS_PER_BLOCK 8
#define EDGES_PER_BLOCK (EDGES_PER_WARP * WARPS_PER_BLOCK)
__global__ void __launch_bounds__(256) aggregate_kernel(
    const float* __restrict__ w_ij,
    float*       __restrict__ out)
{
    __shared__ int4 smeta[EDGES_PER_BLOCK];
    int t = threadIdx.x;
    int gg = blockIdx.x * 256 + t;
    if (gg < N_NODES) g_cnt[gg] = 0;             // reset for next identical call

    int wid  = t >> 5;
    int lane = t & 31;
    int mbase = wid * EDGES_PER_WARP;
    int warpBase = blockIdx.x * EDGES_PER_BLOCK + mbase;

    smeta[mbase + lane] = g_meta[warpBase + lane];   // full-warp coalesced stage
    __syncwarp();

    const float4* w4 = reinterpret_cast<const float4*>(w_ij);

    int cur = smeta[mbase].w;
    uint2 qp = __ldg(&g_qh[(size_t)cur * 32 + lane]);
    float2 q01 = __half22float2(*reinterpret_cast<half2*>(&qp.x));
    float2 q23 = __half22float2(*reinterpret_cast<half2*>(&qp.y));
    float4 acc = make_float4(0.f, 0.f, 0.f, 0.f);

#pragma unroll
    for (int e = 0; e < EDGES_PER_WARP; e++) {
        int4 mm = smeta[mbase + e];                                  // LDS broadcast
        float4 we = __ldcs(w4 + (size_t)mm.x * 32 + lane);           // stream
        uint4 kve = __ldg(&g_kv[(size_t)mm.y * 32 + lane]);          // gather
        float phe = __int_as_float(mm.z);

        if (mm.w != cur) {                                           // segment boundary
            float* dst = out + (size_t)cur * F_TOTAL + lane * 4;
            asm volatile("red.global.add.v4.f32 [%0], {%1,%2,%3,%4};"
                         :: "l"(dst), "f"(acc.x), "f"(acc.y), "f"(acc.z), "f"(acc.w));
            cur = mm.w;
            qp = __ldg(&g_qh[(size_t)cur * 32 + lane]);
            q01 = __half22float2(*reinterpret_cast<half2*>(&qp.x));
            q23 = __half22float2(*reinterpret_cast<half2*>(&qp.y));
            acc = make_float4(0.f, 0.f, 0.f, 0.f);
        }

        float2 k01 = __half22float2(*reinterpret_cast<half2*>(&kve.x));
        float2 k23 = __half22float2(*reinterpret_cast<half2*>(&kve.y));
        float2 v01 = __half22float2(*reinterpret_cast<half2*>(&kve.z));
        float2 v23 = __half22float2(*reinterpret_cast<half2*>(&kve.w));

        float part = q01.x * we.x * k01.x + q01.y * we.y * k01.y
                   + q23.x * we.z * k23.x + q23.y * we.w * k23.y;
        part += __shfl_xor_sync(0xFFFFFFFFu, part, 1);
        part += __shfl_xor_sync(0xFFFFFFFFu, part, 2);

        float alpha = part * 0.25f * phe;   // 1/sqrt(16)
        acc.x += alpha * v01.x;
        acc.y += alpha * v01.y;
        acc.z += alpha * v23.x;
        acc.w += alpha * v23.y;
    }
    float* dst = out + (size_t)cur * F_TOTAL + lane * 4;
    asm volatile("red.global.add.v4.f32 [%0], {%1,%2,%3,%4};"
                 :: "l"(dst), "f"(acc.x), "f"(acc.y), "f"(acc.z), "f"(acc.w));
}

extern "C" void kernel_launch(void* const* d_in, const int* in_sizes, int n_in,
                              void* d_out, int out_size)
{
    const float* x      = (const float*)d_in[0];
    const float* w_ij   = (const float*)d_in[1];
    const int*   idx_i  = (const int*)  d_in[2];
    const int*   idx_j  = (const int*)  d_in[3];
    const float* phi    = (const float*)d_in[4];
    const float* wq     = (const float*)d_in[5];
    const float* wk     = (const float*)d_in[6];
    const float* wv     = (const float*)d_in[7];
    float* out = (float*)d_out;

    projhist_kernel<<<(N_NODES * N_HEADS + 255) / 256, 256>>>(x, wq, wk, wv, idx_i);
    scan1_kernel<<<NB1, 256>>>();
    scatter_kernel<<<(N_PAIRS + 255) / 256, 256>>>(idx_i, idx_j, phi,
                                                   reinterpret_cast<float4*>(out),
                                                   out_size / 4);
    aggregate_kernel<<<N_PAIRS / EDGES_PER_BLOCK, 256>>>(w_ij, out);
}

// round 16
// speedup vs baseline: 1.3910x; 1.0730x over previous
#include <cuda_runtime.h>
#include <cuda_fp16.h>
#include <cstdint>

#define N_NODES 100000
#define N_PAIRS 640000
#define F_TOTAL 128
#define N_HEADS 8
#define HEAD_DIM 16

// q fp16: node n, lane l -> uint2 = q quad (features [4l,4l+4)) as 2x half2.
// kv fp16: node n, lane l -> uint4 = {k quad, v quad}.
__device__ uint2 g_qh[N_NODES * 32];
__device__ uint4 g_kv[N_NODES * 32];

// CSR-by-idx_i machinery.
// g_cnt is zeroed by the TAIL of aggregate_kernel each call (device globals
// start zeroed, so call 1 sees zeros too -> every call does identical work).
__device__ int  g_cnt[N_NODES];
__device__ int  g_cursor[N_NODES];
__device__ int4 g_meta[N_PAIRS];     // {pair_id, idx_j, phi_bits, idx_i} grouped by idx_i
#define NB1 98                        // ceil(100000/1024)
__device__ int g_bsum[NB1];

// proj + histogram fused. WARP-UNIFORM WEIGHTS: warp w == head w, lanes are
// 32 consecutive nodes, so every weight LDS is one broadcast (1 smem phase
// instead of 4) -> 4x less shared-port pressure than the node*8+head mapping.
__global__ void __launch_bounds__(256) projhist_kernel(
    const float* __restrict__ x,
    const float* __restrict__ wq,
    const float* __restrict__ wk,
    const float* __restrict__ wv,
    const int*   __restrict__ idx_i)
{
    __shared__ float sq[N_HEADS * 256];
    __shared__ float sk[N_HEADS * 256];
    __shared__ float sv[N_HEADS * 256];

    int gid = blockIdx.x * 256 + threadIdx.x;
    if (gid < N_PAIRS) atomicAdd(&g_cnt[idx_i[gid]], 1);   // fused histogram

    for (int i = threadIdx.x; i < N_HEADS * HEAD_DIM * HEAD_DIM; i += 256) {
        sq[i] = wq[i];
        sk[i] = wk[i];
        sv[i] = wv[i];
    }
    __syncthreads();

    int wid  = threadIdx.x >> 5;          // head
    int lane = threadIdx.x & 31;
    int n = blockIdx.x * 32 + lane;       // node
    if (n >= N_NODES) return;
    int h = wid;

    const float4* xp = reinterpret_cast<const float4*>(x + (size_t)n * F_TOTAL + h * HEAD_DIM);
    float4 xv0 = __ldg(xp + 0), xv1 = __ldg(xp + 1), xv2 = __ldg(xp + 2), xv3 = __ldg(xp + 3);
    float xr[16] = {xv0.x, xv0.y, xv0.z, xv0.w,
                    xv1.x, xv1.y, xv1.z, xv1.w,
                    xv2.x, xv2.y, xv2.z, xv2.w,
                    xv3.x, xv3.y, xv3.z, xv3.w};

    const float4* wq4 = reinterpret_cast<const float4*>(sq + h * 256);
    const float4* wk4 = reinterpret_cast<const float4*>(sk + h * 256);
    const float4* wv4 = reinterpret_cast<const float4*>(sv + h * 256);

    float qo[16], ko[16], vo[16];
#pragma unroll
    for (int e = 0; e < 16; e++) {
        float aq = 0.f, ak = 0.f, av = 0.f;
#pragma unroll
        for (int d4 = 0; d4 < 4; d4++) {
            float4 a = wq4[e * 4 + d4];   // uniform across warp -> broadcast
            float4 b = wk4[e * 4 + d4];
            float4 c = wv4[e * 4 + d4];
            float x0 = xr[4 * d4 + 0], x1 = xr[4 * d4 + 1];
            float x2 = xr[4 * d4 + 2], x3 = xr[4 * d4 + 3];
            aq += x0 * a.x + x1 * a.y + x2 * a.z + x3 * a.w;
            ak += x0 * b.x + x1 * b.y + x2 * b.z + x3 * b.w;
            av += x0 * c.x + x1 * c.y + x2 * c.z + x3 * c.w;
        }
        qo[e] = aq; ko[e] = ak; vo[e] = av;
    }

    // q: pack 4 uint2 (t=0..3) into 2 aligned uint4 stores
    {
        half2 q01a = __floats2half2_rn(qo[0],  qo[1]);
        half2 q23a = __floats2half2_rn(qo[2],  qo[3]);
        half2 q01b = __floats2half2_rn(qo[4],  qo[5]);
        half2 q23b = __floats2half2_rn(qo[6],  qo[7]);
        half2 q01c = __floats2half2_rn(qo[8],  qo[9]);
        half2 q23c = __floats2half2_rn(qo[10], qo[11]);
        half2 q01d = __floats2half2_rn(qo[12], qo[13]);
        half2 q23d = __floats2half2_rn(qo[14], qo[15]);
        uint4 qa, qb;
        qa.x = *reinterpret_cast<uint32_t*>(&q01a);
        qa.y = *reinterpret_cast<uint32_t*>(&q23a);
        qa.z = *reinterpret_cast<uint32_t*>(&q01b);
        qa.w = *reinterpret_cast<uint32_t*>(&q23b);
        qb.x = *reinterpret_cast<uint32_t*>(&q01c);
        qb.y = *reinterpret_cast<uint32_t*>(&q23c);
        qb.z = *reinterpret_cast<uint32_t*>(&q01d);
        qb.w = *reinterpret_cast<uint32_t*>(&q23d);
        uint4* qdst = reinterpret_cast<uint4*>(&g_qh[(size_t)n * 32 + h * 4]);
        qdst[0] = qa;
        qdst[1] = qb;
    }

    // kv: 4 uint4 stores (t=0..3), consecutive 16B -> full sectors
#pragma unroll
    for (int t = 0; t < 4; t++) {
        half2 k01 = __floats2half2_rn(ko[4*t + 0], ko[4*t + 1]);
        half2 k23 = __floats2half2_rn(ko[4*t + 2], ko[4*t + 3]);
        half2 v01 = __floats2half2_rn(vo[4*t + 0], vo[4*t + 1]);
        half2 v23 = __floats2half2_rn(vo[4*t + 2], vo[4*t + 3]);
        uint4 kvp;
        kvp.x = *reinterpret_cast<uint32_t*>(&k01);
        kvp.y = *reinterpret_cast<uint32_t*>(&k23);
        kvp.z = *reinterpret_cast<uint32_t*>(&v01);
        kvp.w = *reinterpret_cast<uint32_t*>(&v23);
        g_kv[(size_t)n * 32 + h * 4 + t] = kvp;
    }
}

// per-block (1024-element) exclusive scan of g_cnt into g_cursor; raw totals to g_bsum
__global__ void __launch_bounds__(256) scan1_kernel()
{
    __shared__ int sh[256];
    int t = threadIdx.x;
    int base = blockIdx.x * 1024 + t * 4;
    int v0 = (base + 0 < N_NODES) ? g_cnt[base + 0] : 0;
    int v1 = (base + 1 < N_NODES) ? g_cnt[base + 1] : 0;
    int v2 = (base + 2 < N_NODES) ? g_cnt[base + 2] : 0;
    int v3 = (base + 3 < N_NODES) ? g_cnt[base + 3] : 0;
    int s = v0 + v1 + v2 + v3;
    sh[t] = s;
    __syncthreads();
    for (int off = 1; off < 256; off <<= 1) {
        int add = (t >= off) ? sh[t - off] : 0;
        __syncthreads();
        sh[t] += add;
        __syncthreads();
    }
    int excl = sh[t] - s;
    if (base + 0 < N_NODES) g_cursor[base + 0] = excl;
    if (base + 1 < N_NODES) g_cursor[base + 1] = excl + v0;
    if (base + 2 < N_NODES) g_cursor[base + 2] = excl + v0 + v1;
    if (base + 3 < N_NODES) g_cursor[base + 3] = excl + v0 + v1 + v2;
    if (t == 255) g_bsum[blockIdx.x] = sh[255];
}

// scatter (with redundant 98-entry chunk-offset scan) + fused zeroing of out.
__global__ void __launch_bounds__(256) scatter_kernel(
    const int* __restrict__ idx_i,
    const int* __restrict__ idx_j,
    const float* __restrict__ phi,
    float4*    __restrict__ out4,
    int n4)
{
    __shared__ int sh[128];
    __shared__ int sexcl[128];
    int t = threadIdx.x;
    int p = blockIdx.x * 256 + t;

    float4 z = make_float4(0.f, 0.f, 0.f, 0.f);
#pragma unroll
    for (int r = 0; r < 5; r++) {
        int o = p + r * N_PAIRS;
        if (o < n4) out4[o] = z;
    }

    int v = 0;
    if (t < 128) {
        v = (t < NB1) ? g_bsum[t] : 0;
        sh[t] = v;
    }
    __syncthreads();
    for (int off = 1; off < 128; off <<= 1) {
        int add = 0;
        if (t < 128 && t >= off) add = sh[t - off];
        __syncthreads();
        if (t < 128) sh[t] += add;
        __syncthreads();
    }
    if (t < 128) sexcl[t] = sh[t] - v;
    __syncthreads();

    if (p < N_PAIRS) {
        int i = idx_i[p];
        int pos = atomicAdd(&g_cursor[i], 1) + sexcl[i >> 10];
        g_meta[pos] = make_int4(p, idx_j[p], __float_as_int(phi[p]), i);
    }
}

// Edge-parallel segmented reduction (unchanged) + g_cnt reset.
#define EDGES_PER_WARP 32
#define WARPS_PER_BLOCK 8
#define EDGES_PER_BLOCK (EDGES_PER_WARP * WARPS_PER_BLOCK)
__global__ void __launch_bounds__(256) aggregate_kernel(
    const float* __restrict__ w_ij,
    float*       __restrict__ out)
{
    __shared__ int4 smeta[EDGES_PER_BLOCK];
    int t = threadIdx.x;
    int gg = blockIdx.x * 256 + t;
    if (gg < N_NODES) g_cnt[gg] = 0;             // reset for next identical call

    int wid  = t >> 5;
    int lane = t & 31;
    int mbase = wid * EDGES_PER_WARP;
    int warpBase = blockIdx.x * EDGES_PER_BLOCK + mbase;

    smeta[mbase + lane] = g_meta[warpBase + lane];   // full-warp coalesced stage
    __syncwarp();

    const float4* w4 = reinterpret_cast<const float4*>(w_ij);

    int cur = smeta[mbase].w;
    uint2 qp = __ldg(&g_qh[(size_t)cur * 32 + lane]);
    float2 q01 = __half22float2(*reinterpret_cast<half2*>(&qp.x));
    float2 q23 = __half22float2(*reinterpret_cast<half2*>(&qp.y));
    float4 acc = make_float4(0.f, 0.f, 0.f, 0.f);

#pragma unroll
    for (int e = 0; e < EDGES_PER_WARP; e++) {
        int4 mm = smeta[mbase + e];                                  // LDS broadcast
        float4 we = __ldcs(w4 + (size_t)mm.x * 32 + lane);           // stream
        uint4 kve = __ldg(&g_kv[(size_t)mm.y * 32 + lane]);          // gather
        float phe = __int_as_float(mm.z);

        if (mm.w != cur) {                                           // segment boundary
            float* dst = out + (size_t)cur * F_TOTAL + lane * 4;
            asm volatile("red.global.add.v4.f32 [%0], {%1,%2,%3,%4};"
                         :: "l"(dst), "f"(acc.x), "f"(acc.y), "f"(acc.z), "f"(acc.w));
            cur = mm.w;
            qp = __ldg(&g_qh[(size_t)cur * 32 + lane]);
            q01 = __half22float2(*reinterpret_cast<half2*>(&qp.x));
            q23 = __half22float2(*reinterpret_cast<half2*>(&qp.y));
            acc = make_float4(0.f, 0.f, 0.f, 0.f);
        }

        float2 k01 = __half22float2(*reinterpret_cast<half2*>(&kve.x));
        float2 k23 = __half22float2(*reinterpret_cast<half2*>(&kve.y));
        float2 v01 = __half22float2(*reinterpret_cast<half2*>(&kve.z));
        float2 v23 = __half22float2(*reinterpret_cast<half2*>(&kve.w));

        float part = q01.x * we.x * k01.x + q01.y * we.y * k01.y
                   + q23.x * we.z * k23.x + q23.y * we.w * k23.y;
        part += __shfl_xor_sync(0xFFFFFFFFu, part, 1);
        part += __shfl_xor_sync(0xFFFFFFFFu, part, 2);

        float alpha = part * 0.25f * phe;   // 1/sqrt(16)
        acc.x += alpha * v01.x;
        acc.y += alpha * v01.y;
        acc.z += alpha * v23.x;
        acc.w += alpha * v23.y;
    }
    float* dst = out + (size_t)cur * F_TOTAL + lane * 4;
    asm volatile("red.global.add.v4.f32 [%0], {%1,%2,%3,%4};"
                 :: "l"(dst), "f"(acc.x), "f"(acc.y), "f"(acc.z), "f"(acc.w));
}

extern "C" void kernel_launch(void* const* d_in, const int* in_sizes, int n_in,
                              void* d_out, int out_size)
{
    const float* x      = (const float*)d_in[0];
    const float* w_ij   = (const float*)d_in[1];
    const int*   idx_i  = (const int*)  d_in[2];
    const int*   idx_j  = (const int*)  d_in[3];
    const float* phi    = (const float*)d_in[4];
    const float* wq     = (const float*)d_in[5];
    const float* wk     = (const float*)d_in[6];
    const float* wv     = (const float*)d_in[7];
    float* out = (float*)d_out;

    projhist_kernel<<<(N_NODES * N_HEADS + 255) / 256, 256>>>(x, wq, wk, wv, idx_i);
    scan1_kernel<<<NB1, 256>>>();
    scatter_kernel<<<(N_PAIRS + 255) / 256, 256>>>(idx_i, idx_j, phi,
                                                   reinterpret_cast<float4*>(out),
                                                   out_size / 4);
    aggregate_kernel<<<N_PAIRS / EDGES_PER_BLOCK, 256>>>(w_ij, out);
}

// round 17
// speedup vs baseline: 1.4748x; 1.0603x over previous
#include <cuda_runtime.h>
#include <cuda_fp16.h>
#include <cstdint>

#define N_NODES 100000
#define N_PAIRS 640000
#define F_TOTAL 128
#define N_HEADS 8
#define HEAD_DIM 16

// q fp16: node n, lane l -> uint2 = q quad (features [4l,4l+4)) as 2x half2.
// kv fp16: node n, lane l -> uint4 = {k quad, v quad}.
__device__ uint2 g_qh[N_NODES * 32];
__device__ uint4 g_kv[N_NODES * 32];

// CSR-by-idx_i machinery. g_cnt zeroed by aggregate tail each call.
__device__ int  g_cnt[N_NODES];
__device__ int  g_cursor[N_NODES];
__device__ int4 g_meta[N_PAIRS];     // {pair_id, idx_j, phi_bits, idx_i} grouped by idx_i
#define NB1 98                        // ceil(100000/1024)
__device__ int g_bsum[NB1];

// dynamic smem layout for projhist:
//   [0, 24576)            weights: wq | wk | wv, 2048 floats each
//   [24576, ...) union of:
//       x tile   : 32 rows * 132 floats (528B rows, 16B-aligned, conflict-lite)
//       staging  : soq 32*17 uint4 (8704B) then sokv 32*33 uint4 (16896B)
#define SMEM_W     0
#define SMEM_UNION 24576
#define SMEM_SOKV_OFF (SMEM_UNION + 8704)
#define SMEM_TOTAL_PROJ (24576 + 25600)   // 50176

__global__ void __launch_bounds__(256) projhist_kernel(
    const float* __restrict__ x,
    const float* __restrict__ wq,
    const float* __restrict__ wk,
    const float* __restrict__ wv,
    const int*   __restrict__ idx_i)
{
    extern __shared__ char sbuf[];
    float* sw  = reinterpret_cast<float*>(sbuf + SMEM_W);
    float* sx  = reinterpret_cast<float*>(sbuf + SMEM_UNION);
    uint4* soq = reinterpret_cast<uint4*>(sbuf + SMEM_UNION);
    uint4* sokv= reinterpret_cast<uint4*>(sbuf + SMEM_SOKV_OFF);

    int tid = threadIdx.x;
    int gid = blockIdx.x * 256 + tid;
    if (gid < N_PAIRS) atomicAdd(&g_cnt[idx_i[gid]], 1);   // fused histogram

    // weights -> smem
    for (int i = tid; i < 2048; i += 256) {
        sw[i]        = wq[i];
        sw[2048 + i] = wk[i];
        sw[4096 + i] = wv[i];
    }

    // x tile (32 nodes x 128 floats) -> smem, fully coalesced
    int base = blockIdx.x * 32;
    const float4* x4 = reinterpret_cast<const float4*>(x);
#pragma unroll
    for (int r = 0; r < 4; r++) {
        int i4  = tid + r * 256;          // 0..1023
        int row = i4 >> 5;
        int c4  = i4 & 31;
        float4 v = __ldg(x4 + (size_t)(base + row) * 32 + c4);
        *reinterpret_cast<float4*>(sx + row * 132 + c4 * 4) = v;
    }
    __syncthreads();

    // compute: warp = head, lane = node within tile
    int h    = tid >> 5;
    int lane = tid & 31;

    float xr[16];
    {
        const float4* xrow = reinterpret_cast<const float4*>(sx + lane * 132 + h * HEAD_DIM);
        float4 a = xrow[0], b = xrow[1], c = xrow[2], d = xrow[3];
        xr[0]=a.x; xr[1]=a.y; xr[2]=a.z; xr[3]=a.w;
        xr[4]=b.x; xr[5]=b.y; xr[6]=b.z; xr[7]=b.w;
        xr[8]=c.x; xr[9]=c.y; xr[10]=c.z; xr[11]=c.w;
        xr[12]=d.x; xr[13]=d.y; xr[14]=d.z; xr[15]=d.w;
    }

    const float4* wq4 = reinterpret_cast<const float4*>(sw + h * 256);
    const float4* wk4 = reinterpret_cast<const float4*>(sw + 2048 + h * 256);
    const float4* wv4 = reinterpret_cast<const float4*>(sw + 4096 + h * 256);

    float qo[16], ko[16], vo[16];
#pragma unroll
    for (int e = 0; e < 16; e++) {
        float aq = 0.f, ak = 0.f, av = 0.f;
#pragma unroll
        for (int d4 = 0; d4 < 4; d4++) {
            float4 a = wq4[e * 4 + d4];   // warp-uniform -> broadcast
            float4 b = wk4[e * 4 + d4];
            float4 c = wv4[e * 4 + d4];
            float x0 = xr[4 * d4 + 0], x1 = xr[4 * d4 + 1];
            float x2 = xr[4 * d4 + 2], x3 = xr[4 * d4 + 3];
            aq += x0 * a.x + x1 * a.y + x2 * a.z + x3 * a.w;
            ak += x0 * b.x + x1 * b.y + x2 * b.z + x3 * b.w;
            av += x0 * c.x + x1 * c.y + x2 * c.z + x3 * c.w;
        }
        qo[e] = aq; ko[e] = ak; vo[e] = av;
    }
    __syncthreads();   // x reads done -> safe to overwrite union with staging

    // stage q (2 uint4) and kv (4 uint4) into padded smem rows
    {
        half2 q01a = __floats2half2_rn(qo[0],  qo[1]);
        half2 q23a = __floats2half2_rn(qo[2],  qo[3]);
        half2 q01b = __floats2half2_rn(qo[4],  qo[5]);
        half2 q23b = __floats2half2_rn(qo[6],  qo[7]);
        half2 q01c = __floats2half2_rn(qo[8],  qo[9]);
        half2 q23c = __floats2half2_rn(qo[10], qo[11]);
        half2 q01d = __floats2half2_rn(qo[12], qo[13]);
        half2 q23d = __floats2half2_rn(qo[14], qo[15]);
        uint4 qa, qb;
        qa.x = *reinterpret_cast<uint32_t*>(&q01a);
        qa.y = *reinterpret_cast<uint32_t*>(&q23a);
        qa.z = *reinterpret_cast<uint32_t*>(&q01b);
        qa.w = *reinterpret_cast<uint32_t*>(&q23b);
        qb.x = *reinterpret_cast<uint32_t*>(&q01c);
        qb.y = *reinterpret_cast<uint32_t*>(&q23c);
        qb.z = *reinterpret_cast<uint32_t*>(&q01d);
        qb.w = *reinterpret_cast<uint32_t*>(&q23d);
        soq[lane * 17 + h * 2 + 0] = qa;
        soq[lane * 17 + h * 2 + 1] = qb;
    }
#pragma unroll
    for (int t = 0; t < 4; t++) {
        half2 k01 = __floats2half2_rn(ko[4*t + 0], ko[4*t + 1]);
        half2 k23 = __floats2half2_rn(ko[4*t + 2], ko[4*t + 3]);
        half2 v01 = __floats2half2_rn(vo[4*t + 0], vo[4*t + 1]);
        half2 v23 = __floats2half2_rn(vo[4*t + 2], vo[4*t + 3]);
        uint4 kvp;
        kvp.x = *reinterpret_cast<uint32_t*>(&k01);
        kvp.y = *reinterpret_cast<uint32_t*>(&k23);
        kvp.z = *reinterpret_cast<uint32_t*>(&v01);
        kvp.w = *reinterpret_cast<uint32_t*>(&v23);
        sokv[lane * 33 + h * 4 + t] = kvp;
    }
    __syncthreads();

    // coalesced writeback
    uint4* gq4 = reinterpret_cast<uint4*>(g_qh);
#pragma unroll
    for (int r = 0; r < 2; r++) {
        int i  = tid + r * 256;          // 0..511
        int row = i >> 4;
        int col = i & 15;
        gq4[(size_t)(base + row) * 16 + col] = soq[row * 17 + col];
    }
#pragma unroll
    for (int r = 0; r < 4; r++) {
        int i  = tid + r * 256;          // 0..1023
        int row = i >> 5;
        int col = i & 31;
        g_kv[(size_t)(base + row) * 32 + col] = sokv[row * 33 + col];
    }
}

// per-block (1024-element) exclusive scan of g_cnt into g_cursor; raw totals to g_bsum
__global__ void __launch_bounds__(256) scan1_kernel()
{
    __shared__ int sh[256];
    int t = threadIdx.x;
    int base = blockIdx.x * 1024 + t * 4;
    int v0 = (base + 0 < N_NODES) ? g_cnt[base + 0] : 0;
    int v1 = (base + 1 < N_NODES) ? g_cnt[base + 1] : 0;
    int v2 = (base + 2 < N_NODES) ? g_cnt[base + 2] : 0;
    int v3 = (base + 3 < N_NODES) ? g_cnt[base + 3] : 0;
    int s = v0 + v1 + v2 + v3;
    sh[t] = s;
    __syncthreads();
    for (int off = 1; off < 256; off <<= 1) {
        int add = (t >= off) ? sh[t - off] : 0;
        __syncthreads();
        sh[t] += add;
        __syncthreads();
    }
    int excl = sh[t] - s;
    if (base + 0 < N_NODES) g_cursor[base + 0] = excl;
    if (base + 1 < N_NODES) g_cursor[base + 1] = excl + v0;
    if (base + 2 < N_NODES) g_cursor[base + 2] = excl + v0 + v1;
    if (base + 3 < N_NODES) g_cursor[base + 3] = excl + v0 + v1 + v2;
    if (t == 255) g_bsum[blockIdx.x] = sh[255];
}

// scatter (with redundant 98-entry chunk-offset scan) + fused zeroing of out.
__global__ void __launch_bounds__(256) scatter_kernel(
    const int* __restrict__ idx_i,
    const int* __restrict__ idx_j,
    const float* __restrict__ phi,
    float4*    __restrict__ out4,
    int n4)
{
    __shared__ int sh[128];
    __shared__ int sexcl[128];
    int t = threadIdx.x;
    int p = blockIdx.x * 256 + t;

    float4 z = make_float4(0.f, 0.f, 0.f, 0.f);
#pragma unroll
    for (int r = 0; r < 5; r++) {
        int o = p + r * N_PAIRS;
        if (o < n4) out4[o] = z;
    }

    int v = 0;
    if (t < 128) {
        v = (t < NB1) ? g_bsum[t] : 0;
        sh[t] = v;
    }
    __syncthreads();
    for (int off = 1; off < 128; off <<= 1) {
        int add = 0;
        if (t < 128 && t >= off) add = sh[t - off];
        __syncthreads();
        if (t < 128) sh[t] += add;
        __syncthreads();
    }
    if (t < 128) sexcl[t] = sh[t] - v;
    __syncthreads();

    if (p < N_PAIRS) {
        int i = idx_i[p];
        int pos = atomicAdd(&g_cursor[i], 1) + sexcl[i >> 10];
        g_meta[pos] = make_int4(p, idx_j[p], __float_as_int(phi[p]), i);
    }
}

// Edge-parallel segmented reduction (unchanged) + g_cnt reset.
#define EDGES_PER_WARP 32
#define WARPS_PER_BLOCK 8
#define EDGES_PER_BLOCK (EDGES_PER_WARP * WARPS_PER_BLOCK)
__global__ void __launch_bounds__(256) aggregate_kernel(
    const float* __restrict__ w_ij,
    float*       __restrict__ out)
{
    __shared__ int4 smeta[EDGES_PER_BLOCK];
    int t = threadIdx.x;
    int gg = blockIdx.x * 256 + t;
    if (gg < N_NODES) g_cnt[gg] = 0;             // reset for next identical call

    int wid  = t >> 5;
    int lane = t & 31;
    int mbase = wid * EDGES_PER_WARP;
    int warpBase = blockIdx.x * EDGES_PER_BLOCK + mbase;

    smeta[mbase + lane] = g_meta[warpBase + lane];   // full-warp coalesced stage
    __syncwarp();

    const float4* w4 = reinterpret_cast<const float4*>(w_ij);

    int cur = smeta[mbase].w;
    uint2 qp = __ldg(&g_qh[(size_t)cur * 32 + lane]);
    float2 q01 = __half22float2(*reinterpret_cast<half2*>(&qp.x));
    float2 q23 = __half22float2(*reinterpret_cast<half2*>(&qp.y));
    float4 acc = make_float4(0.f, 0.f, 0.f, 0.f);

#pragma unroll
    for (int e = 0; e < EDGES_PER_WARP; e++) {
        int4 mm = smeta[mbase + e];                                  // LDS broadcast
        float4 we = __ldcs(w4 + (size_t)mm.x * 32 + lane);           // stream
        uint4 kve = __ldg(&g_kv[(size_t)mm.y * 32 + lane]);          // gather
        float phe = __int_as_float(mm.z);

        if (mm.w != cur) {                                           // segment boundary
            float* dst = out + (size_t)cur * F_TOTAL + lane * 4;
            asm volatile("red.global.add.v4.f32 [%0], {%1,%2,%3,%4};"
                         :: "l"(dst), "f"(acc.x), "f"(acc.y), "f"(acc.z), "f"(acc.w));
            cur = mm.w;
            qp = __ldg(&g_qh[(size_t)cur * 32 + lane]);
            q01 = __half22float2(*reinterpret_cast<half2*>(&qp.x));
            q23 = __half22float2(*reinterpret_cast<half2*>(&qp.y));
            acc = make_float4(0.f, 0.f, 0.f, 0.f);
        }

        float2 k01 = __half22float2(*reinterpret_cast<half2*>(&kve.x));
        float2 k23 = __half22float2(*reinterpret_cast<half2*>(&kve.y));
        float2 v01 = __half22float2(*reinterpret_cast<half2*>(&kve.z));
        float2 v23 = __half22float2(*reinterpret_cast<half2*>(&kve.w));

        float part = q01.x * we.x * k01.x + q01.y * we.y * k01.y
                   + q23.x * we.z * k23.x + q23.y * we.w * k23.y;
        part += __shfl_xor_sync(0xFFFFFFFFu, part, 1);
        part += __shfl_xor_sync(0xFFFFFFFFu, part, 2);

        float alpha = part * 0.25f * phe;   // 1/sqrt(16)
        acc.x += alpha * v01.x;
        acc.y += alpha * v01.y;
        acc.z += alpha * v23.x;
        acc.w += alpha * v23.y;
    }
    float* dst = out + (size_t)cur * F_TOTAL + lane * 4;
    asm volatile("red.global.add.v4.f32 [%0], {%1,%2,%3,%4};"
                 :: "l"(dst), "f"(acc.x), "f"(acc.y), "f"(acc.z), "f"(acc.w));
}

extern "C" void kernel_launch(void* const* d_in, const int* in_sizes, int n_in,
                              void* d_out, int out_size)
{
    const float* x      = (const float*)d_in[0];
    const float* w_ij   = (const float*)d_in[1];
    const int*   idx_i  = (const int*)  d_in[2];
    const int*   idx_j  = (const int*)  d_in[3];
    const float* phi    = (const float*)d_in[4];
    const float* wq     = (const float*)d_in[5];
    const float* wk     = (const float*)d_in[6];
    const float* wv     = (const float*)d_in[7];
    float* out = (float*)d_out;

    cudaFuncSetAttribute(projhist_kernel,
                         cudaFuncAttributeMaxDynamicSharedMemorySize,
                         SMEM_TOTAL_PROJ);

    projhist_kernel<<<N_NODES / 32, 256, SMEM_TOTAL_PROJ>>>(x, wq, wk, wv, idx_i);
    scan1_kernel<<<NB1, 256>>>();
    scatter_kernel<<<(N_PAIRS + 255) / 256, 256>>>(idx_i, idx_j, phi,
                                                   reinterpret_cast<float4*>(out),
                                                   out_size / 4);
    aggregate_kernel<<<N_PAIRS / EDGES_PER_BLOCK, 256>>>(w_ij, out);
}